// round 5
// baseline (speedup 1.0000x reference)
#include <cuda_runtime.h>
#include <cuda_bf16.h>

#define NBLOCKS 888            // one wave: 148 SMs x 6 CTAs
#define NTHREADS 256
#define NWARPS (NTHREADS / 32)
#define TILE_F4 512            // float4 per tile (2 per thread); 16KB/stream/tile
#define MAX_TILES 16384

__device__ float g_partials[MAX_TILES];
__device__ unsigned int g_tile = 0;
__device__ unsigned int g_count = 0;

// class(x) = clamp(floor(x), -1, 2) + 1  in {0,1,2,3}
__device__ __forceinline__ int cls_of(float x) {
    int i = __float2int_rd(x);
    i = max(i, -1);
    i = min(i, 2);
    return i + 1;
}

__device__ __forceinline__ float quad_term(const float* __restrict__ w,
                                           float4 p, float4 t) {
    float d0 = p.x - t.x;
    float d1 = p.y - t.y;
    float d2 = p.z - t.z;
    float d3 = p.w - t.w;

    float w0 = w[cls_of(t.x) * 4 + cls_of(p.x)];
    float w1 = w[cls_of(t.y) * 4 + cls_of(p.y)];
    float w2 = w[cls_of(t.z) * 4 + cls_of(p.z)];
    float w3 = w[cls_of(t.w) * 4 + cls_of(p.w)];

    float s01 = fmaf(d0 * d0, w0, d1 * d1 * w1);
    float s23 = fmaf(d2 * d2, w2, d3 * d3 * w3);
    return s01 + s23;
}

__global__ void __launch_bounds__(NTHREADS, 6)
gmgs_steal_kernel(const float4* __restrict__ pred,
                  const float4* __restrict__ tru,
                  const float* __restrict__ score,
                  int n4, int ntiles, float inv_B, float* __restrict__ out)
{
    __shared__ float w[32];          // table replicated x2 across bank halves
    __shared__ float swarp[NWARPS];
    __shared__ int s_tile, s_next;
    __shared__ bool s_is_last;

    if (threadIdx.x == 0) {
        float e[16];
        float tot = 0.0f;
        #pragma unroll
        for (int i = 0; i < 16; i++) { e[i] = __expf(-score[i]); tot += e[i]; }
        float inv = 1.0f / tot;
        #pragma unroll
        for (int i = 0; i < 16; i++) { w[i] = e[i] * inv; w[16 + i] = e[i] * inv; }
        s_tile = (int)atomicAdd(&g_tile, 1u);
    }
    __syncthreads();

    const int lane = threadIdx.x & 31;
    const int warp = threadIdx.x >> 5;
    // even lanes read copy0 (banks 0..15), odd lanes copy1 (banks 16..31)
    const float* wl = w + ((lane & 1) << 4);

    int tile = s_tile;
    while (tile < ntiles) {
        if (threadIdx.x == 0) s_next = (int)atomicAdd(&g_tile, 1u);  // prefetch grab

        int base = tile * TILE_F4 + threadIdx.x;
        float acc;
        {
            // 2 float4 per thread per tile, contiguous 8KB coalesced groups.
            int i0 = base;
            int i1 = base + NTHREADS;
            float4 p0 = pred[i0];
            float4 t0 = tru[i0];
            float4 p1 = pred[i1];
            float4 t1 = tru[i1];
            acc = quad_term(wl, p0, t0) + quad_term(wl, p1, t1);
        }

        // Deterministic per-tile block reduction.
        #pragma unroll
        for (int off = 16; off > 0; off >>= 1)
            acc += __shfl_xor_sync(0xFFFFFFFFu, acc, off);
        if (lane == 0) swarp[warp] = acc;
        __syncthreads();
        if (threadIdx.x == 0) {
            float ts = 0.0f;
            #pragma unroll
            for (int k = 0; k < NWARPS; k++) ts += swarp[k];
            g_partials[tile] = ts;
        }
        __syncthreads();
        tile = s_next;
    }

    if (threadIdx.x == 0) {
        __threadfence();
        unsigned int prev = atomicAdd(&g_count, 1u);
        s_is_last = (prev == (unsigned int)(gridDim.x - 1));
    }
    __syncthreads();

    if (s_is_last) {
        // Fixed-order final reduction over per-tile partials: deterministic
        // regardless of which CTA produced each tile.
        float a = 0.0f;
        for (int k = threadIdx.x; k < ntiles; k += NTHREADS)
            a += g_partials[k];
        #pragma unroll
        for (int off = 16; off > 0; off >>= 1)
            a += __shfl_xor_sync(0xFFFFFFFFu, a, off);
        if (lane == 0) swarp[warp] = a;
        __syncthreads();
        if (threadIdx.x == 0) {
            float tot = 0.0f;
            #pragma unroll
            for (int k = 0; k < NWARPS; k++) tot += swarp[k];
            out[0] = tot * inv_B;
            g_tile = 0;   // reset for next graph replay
            g_count = 0;
        }
    }
}

extern "C" void kernel_launch(void* const* d_in, const int* in_sizes, int n_in,
                              void* d_out, int out_size)
{
    const float4* pred  = (const float4*)d_in[0];
    const float4* tru   = (const float4*)d_in[1];
    const float*  score = (const float*)d_in[2];
    float* out = (float*)d_out;

    long n  = (long)in_sizes[0];          // B * T = 524288*48, divisible by 4*TILE_F4
    int  n4 = (int)(n / 4);               // 6291456
    int  ntiles = n4 / TILE_F4;           // 12288 exact
    long B  = n / 48;

    gmgs_steal_kernel<<<NBLOCKS, NTHREADS>>>(pred, tru, score, n4, ntiles,
                                             (float)(1.0 / (double)B), out);
}

// round 6
// speedup vs baseline: 1.0009x; 1.0009x over previous
#include <cuda_runtime.h>
#include <cuda_bf16.h>

// One full wave at max occupancy: 148 SMs x 8 CTAs (regs capped to 32).
#define NBLOCKS 1184
#define NTHREADS 256
#define NWARPS (NTHREADS / 32)
#define STRIDE (NBLOCKS * NTHREADS)   // compile-time: unrolled loads get [R+imm]

__device__ float g_partials[NBLOCKS];
__device__ unsigned int g_count = 0;

// class(x) = clamp(floor(x), -1, 2) + 1  in {0,1,2,3}
__device__ __forceinline__ int cls_of(float x) {
    int i = __float2int_rd(x);   // CVT.RMI
    i = max(i, -1);
    i = min(i, 2);
    return i + 1;
}

__device__ __forceinline__ float quad_term(const float* __restrict__ w,
                                           float4 p, float4 t) {
    float d0 = p.x - t.x;
    float d1 = p.y - t.y;
    float d2 = p.z - t.z;
    float d3 = p.w - t.w;

    float w0 = w[cls_of(t.x) * 4 + cls_of(p.x)];
    float w1 = w[cls_of(t.y) * 4 + cls_of(p.y)];
    float w2 = w[cls_of(t.z) * 4 + cls_of(p.z)];
    float w3 = w[cls_of(t.w) * 4 + cls_of(p.w)];

    float s01 = fmaf(d0 * d0, w0, d1 * d1 * w1);
    float s23 = fmaf(d2 * d2, w2, d3 * d3 * w3);
    return s01 + s23;
}

__global__ void __launch_bounds__(NTHREADS, 8)
gmgs_fused_kernel(const float4* __restrict__ pred,
                  const float4* __restrict__ tru,
                  const float* __restrict__ score,
                  int n4, float inv_B, float* __restrict__ out)
{
    __shared__ float w[32];          // table replicated x2 across bank halves
    __shared__ float swarp[NWARPS];
    __shared__ bool s_is_last;

    if (threadIdx.x == 0) {
        float e[16];
        float tot = 0.0f;
        #pragma unroll
        for (int i = 0; i < 16; i++) { e[i] = __expf(-score[i]); tot += e[i]; }
        float inv = 1.0f / tot;
        #pragma unroll
        for (int i = 0; i < 16; i++) { w[i] = e[i] * inv; w[16 + i] = e[i] * inv; }
    }
    __syncthreads();

    const int lane = threadIdx.x & 31;
    const int warp = threadIdx.x >> 5;
    const float* wl = w + ((lane & 1) << 4);   // even lanes copy0, odd copy1

    float acc0 = 0.0f, acc1 = 0.0f;

    int i = blockIdx.x * NTHREADS + threadIdx.x;
    // 2-way unrolled, compile-time stride: 4 streaming LDG.128 in flight/iter.
    for (; i + STRIDE < n4; i += 2 * STRIDE) {
        float4 p0 = __ldcs(&pred[i]);
        float4 p1 = __ldcs(&pred[i + STRIDE]);
        float4 t0 = __ldcs(&tru[i]);
        float4 t1 = __ldcs(&tru[i + STRIDE]);
        acc0 += quad_term(wl, p0, t0);
        acc1 += quad_term(wl, p1, t1);
    }
    if (i < n4) {
        float4 p0 = __ldcs(&pred[i]);
        float4 t0 = __ldcs(&tru[i]);
        acc0 += quad_term(wl, p0, t0);
    }

    // Deterministic warp tree + cross-warp sum.
    float v = acc0 + acc1;
    #pragma unroll
    for (int off = 16; off > 0; off >>= 1)
        v += __shfl_xor_sync(0xFFFFFFFFu, v, off);
    if (lane == 0) swarp[warp] = v;
    __syncthreads();

    if (threadIdx.x == 0) {
        float bs = 0.0f;
        #pragma unroll
        for (int k = 0; k < NWARPS; k++) bs += swarp[k];
        g_partials[blockIdx.x] = bs;
        __threadfence();
        unsigned int prev = atomicAdd(&g_count, 1u);
        s_is_last = (prev == (unsigned int)(gridDim.x - 1));
    }
    __syncthreads();

    if (s_is_last) {
        // Fixed-order final reduction over 1184 per-CTA partials.
        float a = 0.0f;
        for (int k = threadIdx.x; k < NBLOCKS; k += NTHREADS)
            a += g_partials[k];
        #pragma unroll
        for (int off = 16; off > 0; off >>= 1)
            a += __shfl_xor_sync(0xFFFFFFFFu, a, off);
        if (lane == 0) swarp[warp] = a;
        __syncthreads();
        if (threadIdx.x == 0) {
            float tot = 0.0f;
            #pragma unroll
            for (int k = 0; k < NWARPS; k++) tot += swarp[k];
            out[0] = tot * inv_B;
            g_count = 0;  // reset for next graph replay
        }
    }
}

extern "C" void kernel_launch(void* const* d_in, const int* in_sizes, int n_in,
                              void* d_out, int out_size)
{
    const float4* pred  = (const float4*)d_in[0];
    const float4* tru   = (const float4*)d_in[1];
    const float*  score = (const float*)d_in[2];
    float* out = (float*)d_out;

    long n  = (long)in_sizes[0];   // B * T
    int  n4 = (int)(n / 4);
    long B  = n / 48;              // T = 48

    gmgs_fused_kernel<<<NBLOCKS, NTHREADS>>>(pred, tru, score, n4,
                                             (float)(1.0 / (double)B), out);
}